// round 7
// baseline (speedup 1.0000x reference)
#include <cuda_runtime.h>
#include <math.h>

#define NB 4
#define NT1 16
#define NJ 17
#define NBT 64
#define NBJ 68
#define NROW 1088
#define NV 8000
#define NE 256
#define NH 256
#define NENC 512
#define NS 5
#define EOSI 2

__device__ float d_eo[NBT * NENC];
__device__ float d_pb[2 * NH];
__device__ float d_wpT[NENC * 2 * NH];
__device__ float d_h0c0[NBT * 2 * NH];
__device__ float d_wih0T[512 * 1024];
__device__ float d_whh0T[256 * 1024];
__device__ float d_w1T[512 * 1024];
__device__ float d_fcT[256 * NV];
__device__ float d_xemb[NS * NBJ * NE];
__device__ float d_gx[NS * NBJ * 1024];
__device__ float d_gctx[NBT * 1024];
__device__ float d_h1[NROW * NH];
__device__ float d_c1[NROW * NH];
__device__ float d_h2[NROW * NH];
__device__ float d_c2[NROW * NH];
__device__ float d_g[NROW * 1024];
__device__ float d_pm[32 * NROW];
__device__ float d_ps[32 * NROW];
__device__ float d_lt[NROW];
__device__ float d_le[NROW];
__device__ float d_sel[NS * NROW];
__device__ float d_eosp[NS * NROW];

__device__ __forceinline__ float sigmf(float x) { return 1.f / (1.f + expf(-x)); }

__global__ void k_transpose(const float* __restrict__ in, int N, int K,
                            float* __restrict__ out, int ldOut)
{
    __shared__ float t[32][33];
    int n0 = blockIdx.y * 32, k0 = blockIdx.x * 32;
    int tx = threadIdx.x, ty = threadIdx.y;
    #pragma unroll
    for (int i = 0; i < 32; i += 8) {
        int n = n0 + ty + i, k = k0 + tx;
        t[ty + i][tx] = (n < N && k < K) ? in[(size_t)n * K + k] : 0.f;
    }
    __syncthreads();
    #pragma unroll
    for (int i = 0; i < 32; i += 8) {
        int k = k0 + ty + i, n = n0 + tx;
        if (k < K && n < N) out[(size_t)k * ldOut + n] = t[tx][ty + i];
    }
}

__global__ void k_prep(const float* __restrict__ enc, const float* __restrict__ phb,
                       const float* __restrict__ pcb)
{
    int idx = blockIdx.x * 256 + threadIdx.x;   // 64*512
    int bt = idx >> 9, k = idx & 511;
    int b = bt >> 4, t1 = bt & 15;
    d_eo[idx] = enc[(t1 * NB + b) * NENC + k];
    if (idx < 512) d_pb[idx] = (idx < 256) ? phb[idx] : pcb[idx - 256];
}

__global__ void k_xemb(const int* __restrict__ prev, const float* __restrict__ embed,
                       const float* __restrict__ start_embed)
{
    int idx = blockIdx.x * 256 + threadIdx.x;   // 340*256
    int r = idx >> 8, n = idx & 255;
    int s = r / NBJ, bj = r % NBJ;
    int b = bj / NJ, j = bj % NJ;
    float v;
    if (s == 0) v = start_embed[n];
    else {
        int t = j + s - 1; if (t > 15) t = 15;
        v = embed[(size_t)prev[b * 16 + t] * NE + n];
    }
    d_xemb[idx] = v;
}

__global__ void k_init()
{
    int idx = blockIdx.x * 256 + threadIdx.x;   // 1088*256
    int row = idx >> 8, n = idx & 255;
    int bt = row / NJ;
    d_h1[idx] = d_h0c0[bt * 512 + n];
    d_c1[idx] = d_h0c0[bt * 512 + 256 + n];
    d_h2[idx] = 0.f;
    d_c2[idx] = 0.f;
}

// C[M x Nvalid] = A_spliced[M x K] @ WT([K][ldw], k-major) (+bias)
// k < K1 reads A (lda), k >= K1 reads A2 (lda2). Tile 64x256, 8x8 microtile.
__global__ __launch_bounds__(256) void k_gemm(
    const float* __restrict__ A, int lda,
    const float* __restrict__ A2, int lda2, int K1, int K,
    const float* __restrict__ WT, int ldw, int Nvalid,
    const float* __restrict__ bias,
    float* __restrict__ C, int ldc, int M)
{
    __shared__ float  As[16][68];
    __shared__ float4 Ws[16 * 64];
    int tid = threadIdx.x;
    int n0 = blockIdx.x * 256, r0 = blockIdx.y * 64;
    int tr = tid & 7, tc = tid >> 3;
    int rr = tid >> 2, kk = tid & 3;
    int gr = r0 + rr;
    float acc[8][8];
    #pragma unroll
    for (int i = 0; i < 8; i++)
        #pragma unroll
        for (int j = 0; j < 8; j++) acc[i][j] = 0.f;

    for (int kc = 0; kc < K; kc += 16) {
        int kg = kc + kk * 4;
        float4 av = make_float4(0.f, 0.f, 0.f, 0.f);
        if (gr < M) {
            const float* ap = (kg < K1) ? (A + (size_t)gr * lda + kg)
                                        : (A2 + (size_t)gr * lda2 + (kg - K1));
            av = *(const float4*)ap;
        }
        float4 wv[4];
        #pragma unroll
        for (int j = 0; j < 4; j++) {
            int pos = tid + j * 256;
            int k = pos >> 6, c4 = pos & 63;
            int n = n0 + c4 * 4;
            wv[j] = (n < Nvalid) ? *(const float4*)(WT + (size_t)(kc + k) * ldw + n)
                                 : make_float4(0.f, 0.f, 0.f, 0.f);
        }
        __syncthreads();
        As[kk * 4 + 0][rr] = av.x; As[kk * 4 + 1][rr] = av.y;
        As[kk * 4 + 2][rr] = av.z; As[kk * 4 + 3][rr] = av.w;
        #pragma unroll
        for (int j = 0; j < 4; j++) Ws[tid + j * 256] = wv[j];
        __syncthreads();
        #pragma unroll
        for (int k = 0; k < 16; k++) {
            float4 a0 = *(const float4*)&As[k][tr * 8];
            float4 a1 = *(const float4*)&As[k][tr * 8 + 4];
            float4 w0 = Ws[k * 64 + tc * 2];
            float4 w1 = Ws[k * 64 + tc * 2 + 1];
            float a[8] = {a0.x, a0.y, a0.z, a0.w, a1.x, a1.y, a1.z, a1.w};
            float w[8] = {w0.x, w0.y, w0.z, w0.w, w1.x, w1.y, w1.z, w1.w};
            #pragma unroll
            for (int i = 0; i < 8; i++)
                #pragma unroll
                for (int j = 0; j < 8; j++)
                    acc[i][j] += a[i] * w[j];
        }
        __syncthreads();
    }
    #pragma unroll
    for (int j = 0; j < 8; j++) {
        int n = n0 + tc * 8 + j;
        if (n >= Nvalid) continue;
        float bb = bias ? bias[n] : 0.f;
        #pragma unroll
        for (int i = 0; i < 8; i++) {
            int r = r0 + tr * 8 + i;
            if (r < M) C[(size_t)r * ldc + n] = acc[i][j] + bb;
        }
    }
}

// FC GEMM fused with partial LSE + target/EOS logit gather.
__global__ __launch_bounds__(256) void k_fc(
    const float* __restrict__ Ah2, const float* __restrict__ WT,
    const float* __restrict__ fcb, const int* __restrict__ prev, int s)
{
    __shared__ float  As[16][68];
    __shared__ float4 Ws[16 * 64];
    __shared__ float  red[64][33];
    __shared__ float  rowm[64];
    int tid = threadIdx.x;
    int n0 = blockIdx.x * 256, r0 = blockIdx.y * 64;
    int tr = tid & 7, tc = tid >> 3;
    int rr = tid >> 2, kk = tid & 3;
    float acc[8][8];
    #pragma unroll
    for (int i = 0; i < 8; i++)
        #pragma unroll
        for (int j = 0; j < 8; j++) acc[i][j] = 0.f;

    for (int kc = 0; kc < 256; kc += 16) {
        float4 av = *(const float4*)(Ah2 + (size_t)(r0 + rr) * 256 + kc + kk * 4);
        float4 wv[4];
        #pragma unroll
        for (int j = 0; j < 4; j++) {
            int pos = tid + j * 256;
            int k = pos >> 6, c4 = pos & 63;
            int n = n0 + c4 * 4;
            wv[j] = (n < NV) ? *(const float4*)(WT + (size_t)(kc + k) * NV + n)
                             : make_float4(0.f, 0.f, 0.f, 0.f);
        }
        __syncthreads();
        As[kk * 4 + 0][rr] = av.x; As[kk * 4 + 1][rr] = av.y;
        As[kk * 4 + 2][rr] = av.z; As[kk * 4 + 3][rr] = av.w;
        #pragma unroll
        for (int j = 0; j < 4; j++) Ws[tid + j * 256] = wv[j];
        __syncthreads();
        #pragma unroll
        for (int k = 0; k < 16; k++) {
            float4 a0 = *(const float4*)&As[k][tr * 8];
            float4 a1 = *(const float4*)&As[k][tr * 8 + 4];
            float4 w0 = Ws[k * 64 + tc * 2];
            float4 w1 = Ws[k * 64 + tc * 2 + 1];
            float a[8] = {a0.x, a0.y, a0.z, a0.w, a1.x, a1.y, a1.z, a1.w};
            float w[8] = {w0.x, w0.y, w0.z, w0.w, w1.x, w1.y, w1.z, w1.w};
            #pragma unroll
            for (int i = 0; i < 8; i++)
                #pragma unroll
                for (int j = 0; j < 8; j++)
                    acc[i][j] += a[i] * w[j];
        }
        __syncthreads();
    }
    bool cv[8];
    #pragma unroll
    for (int j = 0; j < 8; j++) {
        int n = n0 + tc * 8 + j;
        cv[j] = n < NV;
        float bb = cv[j] ? fcb[n] : 0.f;
        #pragma unroll
        for (int i = 0; i < 8; i++) acc[i][j] += bb;
    }
    // exact logit gathers (unique writer per row)
    #pragma unroll
    for (int i = 0; i < 8; i++) {
        int r = r0 + tr * 8 + i;
        int b = r / 272, jj = (r % 272) % NJ;
        int t = jj + s; if (t > 15) t = 15;
        int tgtv = (s < 4) ? prev[b * 16 + t] : 0;
        #pragma unroll
        for (int j = 0; j < 8; j++) {
            if (!cv[j]) continue;
            int n = n0 + tc * 8 + j;
            if (n == tgtv) d_lt[r] = acc[i][j];
            if (n == EOSI) d_le[r] = acc[i][j];
        }
    }
    // partial max
    #pragma unroll
    for (int i = 0; i < 8; i++) {
        float m = -INFINITY;
        #pragma unroll
        for (int j = 0; j < 8; j++) if (cv[j]) m = fmaxf(m, acc[i][j]);
        red[tr * 8 + i][tc] = m;
    }
    __syncthreads();
    if (tid < 64) {
        float m = -INFINITY;
        #pragma unroll
        for (int c = 0; c < 32; c++) m = fmaxf(m, red[tid][c]);
        rowm[tid] = m;
    }
    __syncthreads();
    // partial sumexp
    #pragma unroll
    for (int i = 0; i < 8; i++) {
        float m = rowm[tr * 8 + i], ss = 0.f;
        #pragma unroll
        for (int j = 0; j < 8; j++) if (cv[j]) ss += expf(acc[i][j] - m);
        red[tr * 8 + i][tc] = ss;
    }
    __syncthreads();
    if (tid < 64) {
        float ss = 0.f;
        #pragma unroll
        for (int c = 0; c < 32; c++) ss += red[tid][c];
        d_pm[blockIdx.x * NROW + r0 + tid] = rowm[tid];
        d_ps[blockIdx.x * NROW + r0 + tid] = ss;
    }
}

__global__ void k_combine(int s)
{
    int r = blockIdx.x * 256 + threadIdx.x;
    if (r >= NROW) return;
    float m = -INFINITY;
    #pragma unroll
    for (int ct = 0; ct < 32; ct++) m = fmaxf(m, d_pm[ct * NROW + r]);
    float ss = 0.f;
    #pragma unroll
    for (int ct = 0; ct < 32; ct++) ss += d_ps[ct * NROW + r] * expf(d_pm[ct * NROW + r] - m);
    float lse = m + logf(ss);
    d_sel[s * NROW + r]  = d_lt[r] - lse;
    d_eosp[s * NROW + r] = d_le[r] - lse;
}

__global__ void k_cell0(int s)
{
    int idx = blockIdx.x * 256 + threadIdx.x;
    int row = idx >> 8, n = idx & 255;
    int bt = row / NJ, j = row % NJ;
    int bj = (bt >> 4) * NJ + j;
    const float* gr  = d_g    + (size_t)row * 1024;
    const float* gc  = d_gctx + (size_t)bt * 1024;
    const float* gxr = d_gx   + (size_t)(s * NBJ + bj) * 1024;
    float gi = gr[n]       + gc[n]       + gxr[n];
    float gf = gr[n + 256] + gc[n + 256] + gxr[n + 256];
    float gg = gr[n + 512] + gc[n + 512] + gxr[n + 512];
    float go = gr[n + 768] + gc[n + 768] + gxr[n + 768];
    float c = sigmf(gf) * d_c1[idx] + sigmf(gi) * tanhf(gg);
    float h = sigmf(go) * tanhf(c);
    d_c1[idx] = c; d_h1[idx] = h;
}

__global__ void k_cell1()
{
    int idx = blockIdx.x * 256 + threadIdx.x;
    int row = idx >> 8, n = idx & 255;
    const float* gr = d_g + (size_t)row * 1024;
    float c = sigmf(gr[n + 256]) * d_c2[idx] + sigmf(gr[n]) * tanhf(gr[n + 512]);
    float h = sigmf(gr[n + 768]) * tanhf(c);
    d_c2[idx] = c; d_h2[idx] = h;
}

__global__ void k_dp(float* __restrict__ out)
{
    __shared__ float alpha[NB][NJ];
    __shared__ float alphan[NB][NJ];
    int tid = threadIdx.x;
    int b = tid >> 5, t = tid & 31;
    bool act = (b < NB && t < NJ);
    if (act) alpha[b][t] = (t == 0) ? 0.f : -1e30f;
    __syncthreads();
    for (int t1 = 0; t1 < NT1; t1++) {
        if (act) {
            float v[5], m = -INFINITY;
            #pragma unroll
            for (int k = 0; k < 5; k++) {
                if (k <= t) {
                    int j = t - k;
                    int row = (b * NT1 + t1) * NJ + j;
                    float cum = 0.f;
                    for (int ss = 0; ss < k; ss++) cum += d_sel[ss * NROW + row];
                    v[k] = alpha[b][j] + cum + d_eosp[k * NROW + row];
                } else v[k] = -INFINITY;
                m = fmaxf(m, v[k]);
            }
            float ssum = 0.f;
            #pragma unroll
            for (int k = 0; k < 5; k++) ssum += expf(v[k] - m);
            alphan[b][t] = m + logf(ssum);
        }
        __syncthreads();
        if (act) alpha[b][t] = alphan[b][t];
        __syncthreads();
    }
    if (act && t == NT1) out[b] = alpha[b][NT1];
}

extern "C" void kernel_launch(void* const* d_in, const int* in_sizes, int n_in,
                              void* d_out, int out_size)
{
    const int*   prev   = (const int*)  d_in[0];
    const float* enc    = (const float*)d_in[1];
    const float* embed  = (const float*)d_in[2];
    const float* stemb  = (const float*)d_in[3];
    const float* phw    = (const float*)d_in[4];
    const float* phb    = (const float*)d_in[5];
    const float* pcw    = (const float*)d_in[6];
    const float* pcb    = (const float*)d_in[7];
    const float* wih0   = (const float*)d_in[8];
    const float* whh0   = (const float*)d_in[9];
    const float* b0     = (const float*)d_in[10];
    const float* wih1   = (const float*)d_in[11];
    const float* whh1   = (const float*)d_in[12];
    const float* b1     = (const float*)d_in[13];
    const float* fcw    = (const float*)d_in[14];
    const float* fcb    = (const float*)d_in[15];
    float* out = (float*)d_out;

    float *p_eo, *p_pb, *p_wpT, *p_h0c0, *p_wih0T, *p_whh0T, *p_w1T, *p_fcT;
    float *p_xemb, *p_gx, *p_gctx, *p_h1, *p_h2, *p_g;
    cudaGetSymbolAddress((void**)&p_eo, d_eo);
    cudaGetSymbolAddress((void**)&p_pb, d_pb);
    cudaGetSymbolAddress((void**)&p_wpT, d_wpT);
    cudaGetSymbolAddress((void**)&p_h0c0, d_h0c0);
    cudaGetSymbolAddress((void**)&p_wih0T, d_wih0T);
    cudaGetSymbolAddress((void**)&p_whh0T, d_whh0T);
    cudaGetSymbolAddress((void**)&p_w1T, d_w1T);
    cudaGetSymbolAddress((void**)&p_fcT, d_fcT);
    cudaGetSymbolAddress((void**)&p_xemb, d_xemb);
    cudaGetSymbolAddress((void**)&p_gx, d_gx);
    cudaGetSymbolAddress((void**)&p_gctx, d_gctx);
    cudaGetSymbolAddress((void**)&p_h1, d_h1);
    cudaGetSymbolAddress((void**)&p_h2, d_h2);
    cudaGetSymbolAddress((void**)&p_g, d_g);

    dim3 tb(32, 8);
    k_prep<<<128, 256>>>(enc, phb, pcb);
    // weight transposes (k-major)
    k_transpose<<<dim3(16, 8),  tb>>>(phw,  256, 512, p_wpT, 512);
    k_transpose<<<dim3(16, 8),  tb>>>(pcw,  256, 512, p_wpT + 256, 512);
    k_transpose<<<dim3(16, 32), tb>>>(wih0, 1024, 512, p_wih0T, 1024);
    k_transpose<<<dim3(8, 32),  tb>>>(whh0, 1024, 256, p_whh0T, 1024);
    k_transpose<<<dim3(8, 32),  tb>>>(wih1, 1024, 256, p_w1T, 1024);
    k_transpose<<<dim3(8, 32),  tb>>>(whh1, 1024, 256, p_w1T + 256 * 1024, 1024);
    k_transpose<<<dim3(8, 250), tb>>>(fcw,  NV, 256, p_fcT, NV);
    // h0|c0 = eo @ [proj_h|proj_c]^T + bias
    k_gemm<<<dim3(2, 1), 256>>>(p_eo, 512, p_eo, 512, 512, 512,
                                p_wpT, 512, 512, p_pb, p_h0c0, 512, NBT);
    // ctx gate preacts (+ b0)
    k_gemm<<<dim3(4, 1), 256>>>(p_h0c0, 512, p_h0c0, 512, 256, 256,
                                p_wih0T, 1024, 1024, b0, p_gctx, 1024, NBT);
    k_xemb<<<340, 256>>>(prev, embed, stemb);
    // x gate preacts, all 5 steps
    k_gemm<<<dim3(4, 6), 256>>>(p_xemb, 256, p_xemb, 256, 256, 256,
                                p_wih0T + 256 * 1024, 1024, 1024, (const float*)0,
                                p_gx, 1024, NS * NBJ);
    k_init<<<1088, 256>>>();

    for (int s = 0; s < NS; s++) {
        // layer0 recurrent part
        k_gemm<<<dim3(4, 17), 256>>>(p_h1, 256, p_h1, 256, 256, 256,
                                     p_whh0T, 1024, 1024, (const float*)0,
                                     p_g, 1024, NROW);
        k_cell0<<<1088, 256>>>(s);
        // layer1 gates: [h1|h2] @ [w_ih1|w_hh1]^T + b1
        k_gemm<<<dim3(4, 17), 256>>>(p_h1, 256, p_h2, 256, 256, 512,
                                     p_w1T, 1024, 1024, b1, p_g, 1024, NROW);
        k_cell1<<<1088, 256>>>();
        k_fc<<<dim3(32, 17), 256>>>(p_h2, p_fcT, fcb, prev, s);
        k_combine<<<5, 256>>>(s);
    }
    k_dp<<<1, 128>>>(out);
}